// round 1
// baseline (speedup 1.0000x reference)
#include <cuda_runtime.h>

#define BSZ 4
#define UE  8
#define RX  128
#define DD  64
#define NBU (BSZ*UE)   // 32

// Scratch: P, B, G each [NBU][RX][DD] floats (1 MB each)
__device__ float g_P[NBU*RX*DD];
__device__ float g_B[NBU*RX*DD];
__device__ float g_G[NBU*RX*DD];

// -------------------------------------------------------------------------
// Kernel 1: precompute per-row vectors.
//   P_i = b1 + W1[:,64:128]  @ x_i + W1[:,256:320] @ m
//   B_j =      W1[:,128:192] @ x_j
//   G_i =      W1[:,0:64]    @ x_i + W1[:,192:256] @ m
// grid = (NBU, 4), 256 threads. Each CTA: one bu, 32 i-rows.
// -------------------------------------------------------------------------
__global__ void __launch_bounds__(256) prep_kernel(
    const float* __restrict__ x,   // [NBU, RX, DD]
    const float* __restrict__ W1,  // [DD, 5*DD]
    const float* __restrict__ b1)  // [DD]
{
    const int bu  = blockIdx.x;
    const int ic0 = blockIdx.y * 32;

    __shared__ float xs[RX*65];    // padded rows to kill bank conflicts
    __shared__ float ms[DD];

    const float* xp = x + (size_t)bu * RX * DD;
    for (int t = threadIdx.x; t < RX*DD; t += 256) {
        int r = t >> 6, c = t & 63;
        xs[r*65 + c] = xp[t];
    }
    __syncthreads();

    if (threadIdx.x < DD) {
        float s = 0.f;
        #pragma unroll 8
        for (int r = 0; r < RX; r++) s += xs[r*65 + threadIdx.x];
        ms[threadIdx.x] = s * (1.f / RX);
    }
    __syncthreads();

    // 32 i * 64 o outputs; lanes of a warp share o (W1 reads broadcast),
    // consecutive i per lane (padded smem -> conflict-free x reads).
    for (int idx = threadIdx.x; idx < 32*DD; idx += 256) {
        const int i = ic0 + (idx & 31);
        const int o = idx >> 5;
        const float* w  = W1 + o * (5*DD);
        const float* xi = xs + i * 65;
        float accP = b1[o], accB = 0.f, accG = 0.f;
        #pragma unroll 8
        for (int k = 0; k < DD; k++) {
            const float xv = xi[k];
            const float mv = ms[k];
            accG += xv * w[k];
            accP += xv * w[DD   + k];
            accB += xv * w[2*DD + k];
            accG += mv * w[3*DD + k];
            accP += mv * w[4*DD + k];
        }
        const int off = (bu*RX + i)*DD + o;
        g_P[off] = accP;
        g_B[off] = accB;
        g_G[off] = accG;
    }
}

// -------------------------------------------------------------------------
// Kernel 2: per cell (i,j): LayerNorm(P_i + B_j (+G_i on diag)) -> relu
//           -> (+bias on diag) -> W2 matvec + b2.
// grid = (RX, NBU), 256 threads (8 warps). CTA owns row i; warp owns
// j = warp, warp+8, ... W2 rows live in registers: lane keeps rows
// lane and lane+32 (128 regs). y broadcast via shuffles.
// -------------------------------------------------------------------------
__global__ void __launch_bounds__(256) main_kernel(
    const float* __restrict__ ln_g, const float* __restrict__ ln_b,
    const float* __restrict__ bias, const float* __restrict__ W2,
    const float* __restrict__ b2,   float* __restrict__ out)
{
    const int i    = blockIdx.x;
    const int bu   = blockIdx.y;
    const int warp = threadIdx.x >> 5;
    const int lane = threadIdx.x & 31;

    // W2 rows (row-major [o][d]) into registers
    float w2a[DD], w2b[DD];
    {
        const float4* ra = (const float4*)(W2 + (size_t)lane * DD);
        const float4* rb = (const float4*)(W2 + (size_t)(lane + 32) * DD);
        #pragma unroll
        for (int q = 0; q < DD/4; q++) {
            float4 va = ra[q];
            w2a[4*q+0] = va.x; w2a[4*q+1] = va.y; w2a[4*q+2] = va.z; w2a[4*q+3] = va.w;
            float4 vb = rb[q];
            w2b[4*q+0] = vb.x; w2b[4*q+1] = vb.y; w2b[4*q+2] = vb.z; w2b[4*q+3] = vb.w;
        }
    }
    const float ga = ln_g[lane], gb = ln_g[lane+32];
    const float ba = ln_b[lane], bb = ln_b[lane+32];
    const float biasa = bias[lane], biasb = bias[lane+32];
    const float b2a = b2[lane], b2b = b2[lane+32];

    const float* Prow = g_P + (size_t)(bu*RX + i)*DD;
    const float* Grow = g_G + (size_t)(bu*RX + i)*DD;
    const float p0 = Prow[lane], p1 = Prow[lane+32];
    const float gd0 = Grow[lane], gd1 = Grow[lane+32];
    const float* Bbase = g_B + (size_t)bu * RX * DD;
    float* obase = out + (size_t)(bu*RX + i) * RX * DD;

    for (int j = warp; j < RX; j += 8) {
        const float* Bj = Bbase + j*DD;
        float h0 = p0 + Bj[lane];
        float h1 = p1 + Bj[lane+32];
        if (j == i) { h0 += gd0; h1 += gd1; }

        // LayerNorm stats over 64 values (2 per lane)
        float s = h0 + h1;
        float q = h0*h0 + h1*h1;
        #pragma unroll
        for (int m = 16; m > 0; m >>= 1) {
            s += __shfl_xor_sync(0xffffffffu, s, m);
            q += __shfl_xor_sync(0xffffffffu, q, m);
        }
        const float mu   = s * (1.f/64.f);
        const float var  = q * (1.f/64.f) - mu*mu;
        const float rstd = rsqrtf(var + 1e-5f);

        float y0 = fmaxf((h0 - mu) * rstd * ga + ba, 0.f);
        float y1 = fmaxf((h1 - mu) * rstd * gb + bb, 0.f);
        if (j == i) { y0 += biasa; y1 += biasb; }

        // out[o] = b2[o] + sum_d y[d] * W2[o][d]
        // lane k holds y[k] (y0) and y[k+32] (y1)
        float acc0 = b2a, acc1 = b2b;
        #pragma unroll
        for (int k = 0; k < 32; k++) {
            const float ya = __shfl_sync(0xffffffffu, y0, k);
            const float yb = __shfl_sync(0xffffffffu, y1, k);
            acc0 += ya * w2a[k];
            acc1 += ya * w2b[k];
            acc0 += yb * w2a[k+32];
            acc1 += yb * w2b[k+32];
        }
        float* op = obase + (size_t)j * DD;
        op[lane]      = acc0;
        op[lane + 32] = acc1;
    }
}

// -------------------------------------------------------------------------
// Inputs (metadata order): x, W1, b1, ln_g, ln_b, bias, W2, b2
// -------------------------------------------------------------------------
extern "C" void kernel_launch(void* const* d_in, const int* in_sizes, int n_in,
                              void* d_out, int out_size)
{
    const float* x    = (const float*)d_in[0];
    const float* W1   = (const float*)d_in[1];
    const float* b1   = (const float*)d_in[2];
    const float* ln_g = (const float*)d_in[3];
    const float* ln_b = (const float*)d_in[4];
    const float* bias = (const float*)d_in[5];
    const float* W2   = (const float*)d_in[6];
    const float* b2   = (const float*)d_in[7];
    float* out = (float*)d_out;
    (void)in_sizes; (void)n_in; (void)out_size;

    prep_kernel<<<dim3(NBU, 4), 256>>>(x, W1, b1);
    main_kernel<<<dim3(RX, NBU), 256>>>(ln_g, ln_b, bias, W2, b2, out);
}

// round 2
// speedup vs baseline: 1.3033x; 1.3033x over previous
#include <cuda_runtime.h>

#define BSZ 4
#define UE  8
#define RX  128
#define DD  64
#define NBU (BSZ*UE)   // 32

// Scratch: P, B, G each [NBU][RX][DD] floats (1 MB each)
__device__ float g_P[NBU*RX*DD];
__device__ float g_B[NBU*RX*DD];
__device__ float g_G[NBU*RX*DD];

typedef unsigned long long u64;

__device__ __forceinline__ u64 splat2(float y) {
    u64 r; asm("mov.b64 %0, {%1, %1};" : "=l"(r) : "f"(y)); return r;
}
__device__ __forceinline__ u64 packf2(float lo, float hi) {
    u64 r; asm("mov.b64 %0, {%1, %2};" : "=l"(r) : "f"(lo), "f"(hi)); return r;
}
__device__ __forceinline__ void unpackf2(u64 v, float &lo, float &hi) {
    asm("mov.b64 {%0, %1}, %2;" : "=f"(lo), "=f"(hi) : "l"(v));
}
// d = a*b + c, packed fp32x2 (SASS FFMA2)
__device__ __forceinline__ u64 ffma2(u64 a, u64 b, u64 c) {
    u64 d; asm("fma.rn.f32x2 %0, %1, %2, %3;" : "=l"(d) : "l"(a), "l"(b), "l"(c)); return d;
}
__device__ __forceinline__ u64 fadd2(u64 a, u64 b) {
    u64 d; asm("add.rn.f32x2 %0, %1, %2;" : "=l"(d) : "l"(a), "l"(b)); return d;
}

// -------------------------------------------------------------------------
// Kernel 1: precompute per-row vectors.
//   P_i = b1 + W1[:,64:128]  @ x_i + W1[:,256:320] @ m
//   B_j =      W1[:,128:192] @ x_j
//   G_i =      W1[:,0:64]    @ x_i + W1[:,192:256] @ m
// grid = (NBU, 16), 256 threads. Each CTA: one bu, 8 i-rows.
// -------------------------------------------------------------------------
__global__ void __launch_bounds__(256) prep_kernel(
    const float* __restrict__ x,   // [NBU, RX, DD]
    const float* __restrict__ W1,  // [DD, 5*DD]
    const float* __restrict__ b1)  // [DD]
{
    const int bu  = blockIdx.x;
    const int ic0 = blockIdx.y * 8;

    __shared__ float xs[RX*65];    // padded rows -> conflict-free
    __shared__ float msp[4][DD];
    __shared__ float ms[DD];

    const float* xp = x + (size_t)bu * RX * DD;
    for (int t = threadIdx.x; t < RX*DD; t += 256) {
        int r = t >> 6, c = t & 63;
        xs[r*65 + c] = xp[t];
    }
    __syncthreads();

    // mean over 128 rows: 4 partial sums of 32 rows each
    {
        const int col = threadIdx.x & 63;
        const int qr  = threadIdx.x >> 6;       // 0..3
        float s = 0.f;
        #pragma unroll 8
        for (int r = qr*32; r < qr*32 + 32; r++) s += xs[r*65 + col];
        msp[qr][col] = s;
    }
    __syncthreads();
    if (threadIdx.x < DD) {
        ms[threadIdx.x] = (msp[0][threadIdx.x] + msp[1][threadIdx.x] +
                           msp[2][threadIdx.x] + msp[3][threadIdx.x]) * (1.f / RX);
    }
    __syncthreads();

    // 8 i * 64 o = 512 tasks over 256 threads
    for (int idx = threadIdx.x; idx < 8*DD; idx += 256) {
        const int i = ic0 + (idx & 7);
        const int o = idx >> 3;
        const float* w  = W1 + o * (5*DD);
        const float* xi = xs + i * 65;
        float accP = b1[o], accB = 0.f, accG = 0.f;
        #pragma unroll 8
        for (int k = 0; k < DD; k++) {
            const float xv = xi[k];
            const float mv = ms[k];
            accG += xv * w[k];
            accP += xv * w[DD   + k];
            accB += xv * w[2*DD + k];
            accG += mv * w[3*DD + k];
            accP += mv * w[4*DD + k];
        }
        const int off = (bu*RX + i)*DD + o;
        g_P[off] = accP;
        g_B[off] = accB;
        g_G[off] = accG;
    }
}

// -------------------------------------------------------------------------
// Kernel 2: per cell (i,j): LayerNorm(P_i + B_j (+G_i on diag)) -> relu
//           -> (+bias on diag) -> W2 matvec + b2.
// grid = (RX, NBU), 128 threads (4 warps, 3 CTAs/SM). CTA owns row i;
// warp owns j = warp + 4k. W2 packed in registers as f32x2 pairs
// (rows lane, lane+32). y broadcast via pre-splatted smem + LDS.128,
// inner loop is FFMA2.
// -------------------------------------------------------------------------
__global__ void __launch_bounds__(128, 3) main_kernel(
    const float* __restrict__ ln_g, const float* __restrict__ ln_b,
    const float* __restrict__ bias, const float* __restrict__ W2,
    const float* __restrict__ b2,   float* __restrict__ out)
{
    const int i    = blockIdx.x;
    const int bu   = blockIdx.y;
    const int warp = threadIdx.x >> 5;
    const int lane = threadIdx.x & 31;

    __shared__ __align__(16) u64 ys[4][2][DD];   // per-warp, double-buffered

    // W2 rows lane and lane+32 packed into f32x2 pairs
    u64 w2p[DD];
    {
        const float4* ra = (const float4*)(W2 + (size_t)lane * DD);
        const float4* rb = (const float4*)(W2 + (size_t)(lane + 32) * DD);
        #pragma unroll
        for (int q = 0; q < DD/4; q++) {
            float4 va = ra[q];
            float4 vb = rb[q];
            w2p[4*q+0] = packf2(va.x, vb.x);
            w2p[4*q+1] = packf2(va.y, vb.y);
            w2p[4*q+2] = packf2(va.z, vb.z);
            w2p[4*q+3] = packf2(va.w, vb.w);
        }
    }
    const float ga = ln_g[lane], gb = ln_g[lane+32];
    const float ba = ln_b[lane], bb = ln_b[lane+32];
    const float biasa = bias[lane], biasb = bias[lane+32];
    const u64 b2p = packf2(b2[lane], b2[lane+32]);

    const float* Prow = g_P + (size_t)(bu*RX + i)*DD;
    const float* Grow = g_G + (size_t)(bu*RX + i)*DD;
    const float p0 = Prow[lane], p1 = Prow[lane+32];
    const float gd0 = Grow[lane], gd1 = Grow[lane+32];
    const float* Bbase = g_B + (size_t)bu * RX * DD;
    float* obase = out + (size_t)(bu*RX + i) * RX * DD;

    #pragma unroll 1
    for (int jj = 0; jj < RX/4; jj++) {
        const int j = warp + jj*4;
        const float* Bj = Bbase + j*DD;
        float h0 = p0 + Bj[lane];
        float h1 = p1 + Bj[lane+32];
        if (j == i) { h0 += gd0; h1 += gd1; }

        // LayerNorm stats over 64 values (2 per lane)
        float s = h0 + h1;
        float q = h0*h0 + h1*h1;
        #pragma unroll
        for (int m = 16; m > 0; m >>= 1) {
            s += __shfl_xor_sync(0xffffffffu, s, m);
            q += __shfl_xor_sync(0xffffffffu, q, m);
        }
        const float mu   = s * (1.f/64.f);
        const float var  = q * (1.f/64.f) - mu*mu;
        const float rstd = rsqrtf(var + 1e-5f);

        float y0 = fmaxf((h0 - mu) * rstd * ga + ba, 0.f);
        float y1 = fmaxf((h1 - mu) * rstd * gb + bb, 0.f);
        if (j == i) { y0 += biasa; y1 += biasb; }

        // publish pre-splatted y to this warp's smem buffer
        const int buf = jj & 1;
        ys[warp][buf][lane]      = splat2(y0);
        ys[warp][buf][lane + 32] = splat2(y1);
        __syncwarp();

        // matvec: acc(f32x2) over 64 k, LDS.128 broadcast + FFMA2
        const ulonglong2* yv = (const ulonglong2*)ys[warp][buf];
        u64 acc0 = b2p, acc1 = 0ull;
        #pragma unroll
        for (int k2 = 0; k2 < DD/2; k2++) {
            ulonglong2 p = yv[k2];
            acc0 = ffma2(w2p[2*k2+0], p.x, acc0);
            acc1 = ffma2(w2p[2*k2+1], p.y, acc1);
        }
        const u64 acc = fadd2(acc0, acc1);
        float r0, r1; unpackf2(acc, r0, r1);
        float* op = obase + (size_t)j * DD;
        op[lane]      = r0;
        op[lane + 32] = r1;
    }
}

// -------------------------------------------------------------------------
// Inputs (metadata order): x, W1, b1, ln_g, ln_b, bias, W2, b2
// -------------------------------------------------------------------------
extern "C" void kernel_launch(void* const* d_in, const int* in_sizes, int n_in,
                              void* d_out, int out_size)
{
    const float* x    = (const float*)d_in[0];
    const float* W1   = (const float*)d_in[1];
    const float* b1   = (const float*)d_in[2];
    const float* ln_g = (const float*)d_in[3];
    const float* ln_b = (const float*)d_in[4];
    const float* bias = (const float*)d_in[5];
    const float* W2   = (const float*)d_in[6];
    const float* b2   = (const float*)d_in[7];
    float* out = (float*)d_out;
    (void)in_sizes; (void)n_in; (void)out_size;

    prep_kernel<<<dim3(NBU, 16), 256>>>(x, W1, b1);
    main_kernel<<<dim3(RX, NBU), 128>>>(ln_g, ln_b, bias, W2, b2, out);
}